// round 1
// baseline (speedup 1.0000x reference)
#include <cuda_runtime.h>
#include <math.h>

// Problem constants
#define BB   2
#define NN   4096
#define HID  512
#define NH   8
#define HD   64
#define MTOK (BB*NN)          // 8192 tokens
#define QSCALE 0.04419417382415922f   // 1/sqrt(512)

// Scratch (device globals; no allocations allowed)
static __device__ float g_q[(size_t)BB*NH*NN*HD];     // [b,h,n,d]
static __device__ float g_k[(size_t)BB*NH*NN*HD];
static __device__ float g_v[(size_t)BB*NH*NN*HD];
static __device__ float g_attn[(size_t)MTOK*HID];     // [t, h*64+d]

// ---------------------------------------------------------------------------
// Kernel 1: fused QKV projection.  C[t, c] = x[t,:] @ W[:,c] + b[c]
// Tiles: 128(M) x 64(N), k-tile 16. 256 threads, 8x4 micro-tile (strided by 16).
// Grid: x = 24 column tiles (3*512/64), y = 64 row tiles (8192/128).
// ---------------------------------------------------------------------------
__global__ __launch_bounds__(256) void qkv_kernel(
    const float* __restrict__ x,
    const float* __restrict__ Wq, const float* __restrict__ bq,
    const float* __restrict__ Wk, const float* __restrict__ bk,
    const float* __restrict__ Wv, const float* __restrict__ bv)
{
    __shared__ float As[16][129];   // padded transpose: As[k][m]
    __shared__ float Bs[16][64];    // Bs[k][c]

    const int ctile = blockIdx.x * 64;        // 0..1535
    const int wsel  = ctile >> 9;             // 0=q,1=k,2=v
    const int c0    = ctile & 511;
    const float* W    = (wsel==0) ? Wq : ((wsel==1) ? Wk : Wv);
    const float* bias = (wsel==0) ? bq : ((wsel==1) ? bk : bv);
    float* outb       = (wsel==0) ? g_q : ((wsel==1) ? g_k : g_v);
    const float scale = (wsel==0) ? QSCALE : 1.0f;

    const int tm0 = blockIdx.y * 128;
    const int tid = threadIdx.x;
    const int tx  = tid & 15;
    const int ty  = tid >> 4;

    float acc[8][4];
#pragma unroll
    for (int i = 0; i < 8; i++)
#pragma unroll
        for (int j = 0; j < 4; j++) acc[i][j] = 0.0f;

    for (int k0 = 0; k0 < HID; k0 += 16) {
        // Load A tile (128 x 16) transposed into As[k][m]
#pragma unroll
        for (int it = 0; it < 2; it++) {
            int idx = tid + it * 256;            // 512 float4 loads
            int m   = idx >> 2;
            int kg  = idx & 3;
            float4 v = *(const float4*)(x + (size_t)(tm0 + m) * HID + k0 + kg * 4);
            As[kg*4+0][m] = v.x;
            As[kg*4+1][m] = v.y;
            As[kg*4+2][m] = v.z;
            As[kg*4+3][m] = v.w;
        }
        // Load B tile (16 x 64)
        {
            int k  = tid >> 4;
            int cg = tid & 15;
            *(float4*)&Bs[k][cg*4] =
                *(const float4*)(W + (size_t)(k0 + k) * HID + c0 + cg * 4);
        }
        __syncthreads();

#pragma unroll
        for (int k = 0; k < 16; k++) {
            float a[8], b[4];
#pragma unroll
            for (int i = 0; i < 8; i++) a[i] = As[k][ty + 16*i];
#pragma unroll
            for (int j = 0; j < 4; j++) b[j] = Bs[k][tx + 16*j];
#pragma unroll
            for (int i = 0; i < 8; i++)
#pragma unroll
                for (int j = 0; j < 4; j++) acc[i][j] += a[i] * b[j];
        }
        __syncthreads();
    }

    // Epilogue: bias, scale (q only), scatter to [b,h,n,d]
#pragma unroll
    for (int i = 0; i < 8; i++) {
        int t = tm0 + ty + 16*i;
        int b = t >> 12;
        int n = t & (NN - 1);
#pragma unroll
        for (int j = 0; j < 4; j++) {
            int c = c0 + tx + 16*j;             // 0..511 within this weight
            float val = (acc[i][j] + bias[c]) * scale;
            int h = c >> 6;
            int d = c & 63;
            outb[(((size_t)(b * NH + h)) * NN + n) * HD + d] = val;
        }
    }
}

// ---------------------------------------------------------------------------
// Kernel 2: flash attention.  Per block: 128 queries of one (b,h), loop over
// 64-key tiles with online softmax. 256 threads, 8x4 micro tiles.
// Grid: x = B*NH (16), y = N/128 (32). Dynamic smem ~99 KB.
// ---------------------------------------------------------------------------
#define QS_STRIDE 129
#define KS_STRIDE 65
#define PS_STRIDE 129

__global__ __launch_bounds__(256, 2) void attn_kernel(const float* __restrict__ mask)
{
    extern __shared__ float sm[];
    float* Qs  = sm;                         // [64 d][129]  (r = 0..127)
    float* Ks  = Qs  + 64 * QS_STRIDE;       // [64 d][65]   (c = 0..63)
    float* Vs  = Ks  + 64 * KS_STRIDE;       // [64 c][64]   (d = 0..63)
    float* Ps  = Vs  + 64 * 64;              // [64 c][129]  (r = 0..127)
    float* mks = Ps  + 64 * PS_STRIDE;       // [64]

    const int bh  = blockIdx.x;
    const int b   = bh >> 3;
    const int h   = bh & 7;
    const int qt0 = blockIdx.y * 128;
    const int tid = threadIdx.x;
    const int tx  = tid & 15;
    const int ty  = tid >> 4;

    const float* qb = g_q + (size_t)bh * NN * HD;
    const float* kb = g_k + (size_t)bh * NN * HD;
    const float* vb = g_v + (size_t)bh * NN * HD;
    const float* mb = mask + (size_t)b * NN;

    // Load Q tile (128 x 64) transposed into Qs[d][r]
    for (int idx = tid; idx < 128 * 16; idx += 256) {
        int r  = idx >> 4;
        int dg = idx & 15;
        float4 v = *(const float4*)(qb + (size_t)(qt0 + r) * HD + dg * 4);
        Qs[(dg*4+0)*QS_STRIDE + r] = v.x;
        Qs[(dg*4+1)*QS_STRIDE + r] = v.y;
        Qs[(dg*4+2)*QS_STRIDE + r] = v.z;
        Qs[(dg*4+3)*QS_STRIDE + r] = v.w;
    }

    float mrow[8], lrow[8], mq[8];
    float o[8][4];
#pragma unroll
    for (int i = 0; i < 8; i++) {
        mrow[i] = -1e30f;
        lrow[i] = 0.0f;
        mq[i]   = mb[qt0 + ty + 16*i];
#pragma unroll
        for (int j = 0; j < 4; j++) o[i][j] = 0.0f;
    }
    __syncthreads();

    for (int kt0 = 0; kt0 < NN; kt0 += 64) {
        // Load K tile transposed Ks[d][c], V tile natural Vs[c][d], mask
        for (int idx = tid; idx < 64 * 16; idx += 256) {
            int c  = idx >> 4;
            int dg = idx & 15;
            float4 v = *(const float4*)(kb + (size_t)(kt0 + c) * HD + dg * 4);
            Ks[(dg*4+0)*KS_STRIDE + c] = v.x;
            Ks[(dg*4+1)*KS_STRIDE + c] = v.y;
            Ks[(dg*4+2)*KS_STRIDE + c] = v.z;
            Ks[(dg*4+3)*KS_STRIDE + c] = v.w;
            float4 w = *(const float4*)(vb + (size_t)(kt0 + c) * HD + dg * 4);
            *(float4*)&Vs[c*64 + dg*4] = w;
        }
        if (tid < 64) mks[tid] = mb[kt0 + tid];
        __syncthreads();

        // S = Q @ K^T  (128 x 64 tile)
        float s[8][4];
#pragma unroll
        for (int i = 0; i < 8; i++)
#pragma unroll
            for (int j = 0; j < 4; j++) s[i][j] = 0.0f;

#pragma unroll 8
        for (int d = 0; d < 64; d++) {
            float a[8], bb[4];
#pragma unroll
            for (int i = 0; i < 8; i++) a[i] = Qs[d*QS_STRIDE + ty + 16*i];
#pragma unroll
            for (int j = 0; j < 4; j++) bb[j] = Ks[d*KS_STRIDE + tx + 16*j];
#pragma unroll
            for (int i = 0; i < 8; i++)
#pragma unroll
                for (int j = 0; j < 4; j++) s[i][j] += a[i] * bb[j];
        }

        // mask bias + online softmax
        float mk[4];
#pragma unroll
        for (int j = 0; j < 4; j++) mk[j] = mks[tx + 16*j];

#pragma unroll
        for (int i = 0; i < 8; i++) {
#pragma unroll
            for (int j = 0; j < 4; j++)
                s[i][j] += (1.0f - mq[i] * mk[j]) * (-1.0e6f);

            float tmax = fmaxf(fmaxf(s[i][0], s[i][1]), fmaxf(s[i][2], s[i][3]));
#pragma unroll
            for (int off = 8; off >= 1; off >>= 1)
                tmax = fmaxf(tmax, __shfl_xor_sync(0xffffffffu, tmax, off, 16));

            float mnew = fmaxf(mrow[i], tmax);
            float fac  = __expf(mrow[i] - mnew);
            float rsum = 0.0f;
#pragma unroll
            for (int j = 0; j < 4; j++) {
                s[i][j] = __expf(s[i][j] - mnew);
                rsum += s[i][j];
            }
#pragma unroll
            for (int off = 8; off >= 1; off >>= 1)
                rsum += __shfl_xor_sync(0xffffffffu, rsum, off, 16);

            lrow[i] = lrow[i] * fac + rsum;
            mrow[i] = mnew;
#pragma unroll
            for (int j = 0; j < 4; j++) {
                o[i][j] *= fac;
                Ps[(tx + 16*j) * PS_STRIDE + ty + 16*i] = s[i][j];
            }
        }
        __syncthreads();

        // O += P @ V
#pragma unroll 8
        for (int c = 0; c < 64; c++) {
            float a[8], bb[4];
#pragma unroll
            for (int i = 0; i < 8; i++) a[i] = Ps[c*PS_STRIDE + ty + 16*i];
#pragma unroll
            for (int j = 0; j < 4; j++) bb[j] = Vs[c*64 + tx + 16*j];
#pragma unroll
            for (int i = 0; i < 8; i++)
#pragma unroll
                for (int j = 0; j < 4; j++) o[i][j] += a[i] * bb[j];
        }
        __syncthreads();
    }

    // Write normalized output to [t, h*64 + d]
#pragma unroll
    for (int i = 0; i < 8; i++) {
        int r = qt0 + ty + 16*i;
        float inv = 1.0f / lrow[i];
#pragma unroll
        for (int j = 0; j < 4; j++) {
            g_attn[((size_t)(b * NN + r)) * HID + h * HD + tx + 16*j] = o[i][j] * inv;
        }
    }
}

// ---------------------------------------------------------------------------
// Kernel 3: output projection. out[t,c] = g_attn[t,:] @ Wo[:,c] + bo[c]
// Grid: x = 8 column tiles, y = 64 row tiles.
// ---------------------------------------------------------------------------
__global__ __launch_bounds__(256) void proj_kernel(
    const float* __restrict__ Wo, const float* __restrict__ bo,
    float* __restrict__ out)
{
    __shared__ float As[16][129];
    __shared__ float Bs[16][64];

    const int c0  = blockIdx.x * 64;
    const int tm0 = blockIdx.y * 128;
    const int tid = threadIdx.x;
    const int tx  = tid & 15;
    const int ty  = tid >> 4;

    float acc[8][4];
#pragma unroll
    for (int i = 0; i < 8; i++)
#pragma unroll
        for (int j = 0; j < 4; j++) acc[i][j] = 0.0f;

    for (int k0 = 0; k0 < HID; k0 += 16) {
#pragma unroll
        for (int it = 0; it < 2; it++) {
            int idx = tid + it * 256;
            int m   = idx >> 2;
            int kg  = idx & 3;
            float4 v = *(const float4*)(g_attn + (size_t)(tm0 + m) * HID + k0 + kg * 4);
            As[kg*4+0][m] = v.x;
            As[kg*4+1][m] = v.y;
            As[kg*4+2][m] = v.z;
            As[kg*4+3][m] = v.w;
        }
        {
            int k  = tid >> 4;
            int cg = tid & 15;
            *(float4*)&Bs[k][cg*4] =
                *(const float4*)(Wo + (size_t)(k0 + k) * HID + c0 + cg * 4);
        }
        __syncthreads();

#pragma unroll
        for (int k = 0; k < 16; k++) {
            float a[8], b[4];
#pragma unroll
            for (int i = 0; i < 8; i++) a[i] = As[k][ty + 16*i];
#pragma unroll
            for (int j = 0; j < 4; j++) b[j] = Bs[k][tx + 16*j];
#pragma unroll
            for (int i = 0; i < 8; i++)
#pragma unroll
                for (int j = 0; j < 4; j++) acc[i][j] += a[i] * b[j];
        }
        __syncthreads();
    }

#pragma unroll
    for (int i = 0; i < 8; i++) {
        int t = tm0 + ty + 16*i;
#pragma unroll
        for (int j = 0; j < 4; j++) {
            int c = c0 + tx + 16*j;
            out[(size_t)t * HID + c] = acc[i][j] + bo[c];
        }
    }
}

// ---------------------------------------------------------------------------
extern "C" void kernel_launch(void* const* d_in, const int* in_sizes, int n_in,
                              void* d_out, int out_size)
{
    const float* x    = (const float*)d_in[0];
    const float* mask = (const float*)d_in[1];
    const float* Wq   = (const float*)d_in[2];
    const float* bq   = (const float*)d_in[3];
    const float* Wk   = (const float*)d_in[4];
    const float* bk   = (const float*)d_in[5];
    const float* Wv   = (const float*)d_in[6];
    const float* bv   = (const float*)d_in[7];
    const float* Wo   = (const float*)d_in[8];
    const float* bo   = (const float*)d_in[9];
    float* out = (float*)d_out;

    const int attn_smem = (64*QS_STRIDE + 64*KS_STRIDE + 64*64 + 64*PS_STRIDE + 64)
                          * (int)sizeof(float);
    cudaFuncSetAttribute(attn_kernel,
                         cudaFuncAttributeMaxDynamicSharedMemorySize, attn_smem);

    dim3 qkv_grid(24, MTOK / 128);
    qkv_kernel<<<qkv_grid, 256>>>(x, Wq, bq, Wk, bk, Wv, bv);

    dim3 attn_grid(BB * NH, NN / 128);
    attn_kernel<<<attn_grid, 256, attn_smem>>>(mask);

    dim3 proj_grid(HID / 64, MTOK / 128);
    proj_kernel<<<proj_grid, 256>>>(Wo, bo, out);
}

// round 2
// speedup vs baseline: 2.4647x; 2.4647x over previous
#include <cuda_runtime.h>
#include <math.h>

// Problem constants
#define BB   2
#define NN   4096
#define HID  512
#define NH   8
#define HD   64
#define MTOK (BB*NN)          // 8192 tokens
#define QSCALE 0.04419417382415922f   // 1/sqrt(512)

// Scratch (device globals; no allocations allowed)
static __device__ float g_q[(size_t)BB*NH*NN*HD];     // [b,h,n,d]  tf32-rounded
static __device__ float g_k[(size_t)BB*NH*NN*HD];     // tf32-rounded
static __device__ float g_v[(size_t)BB*NH*NN*HD];     // tf32-rounded
static __device__ float g_attn[(size_t)MTOK*HID];     // [t, h*64+d] fp32

// ---------------------------------------------------------------------------
// Helpers
// ---------------------------------------------------------------------------
__device__ __forceinline__ unsigned f2tf(float f) {
    unsigned u;
    asm("cvt.rna.tf32.f32 %0, %1;" : "=r"(u) : "f"(f));
    return u;
}

__device__ __forceinline__ void mma_tf32(float* d, const unsigned* a, const unsigned* b) {
    asm volatile(
        "mma.sync.aligned.m16n8k8.row.col.f32.tf32.tf32.f32 "
        "{%0,%1,%2,%3}, {%4,%5,%6,%7}, {%8,%9}, {%0,%1,%2,%3};"
        : "+f"(d[0]), "+f"(d[1]), "+f"(d[2]), "+f"(d[3])
        : "r"(a[0]), "r"(a[1]), "r"(a[2]), "r"(a[3]), "r"(b[0]), "r"(b[1]));
}

// ---------------------------------------------------------------------------
// Kernel 1: fused QKV projection (SIMT fp32). Epilogue rounds to tf32.
// ---------------------------------------------------------------------------
__global__ __launch_bounds__(256) void qkv_kernel(
    const float* __restrict__ x,
    const float* __restrict__ Wq, const float* __restrict__ bq,
    const float* __restrict__ Wk, const float* __restrict__ bk,
    const float* __restrict__ Wv, const float* __restrict__ bv)
{
    __shared__ float As[16][129];   // padded transpose: As[k][m]
    __shared__ float Bs[16][64];    // Bs[k][c]

    const int ctile = blockIdx.x * 64;
    const int wsel  = ctile >> 9;             // 0=q,1=k,2=v
    const int c0    = ctile & 511;
    const float* W    = (wsel==0) ? Wq : ((wsel==1) ? Wk : Wv);
    const float* bias = (wsel==0) ? bq : ((wsel==1) ? bk : bv);
    float* outb       = (wsel==0) ? g_q : ((wsel==1) ? g_k : g_v);
    const float scale = (wsel==0) ? QSCALE : 1.0f;

    const int tm0 = blockIdx.y * 128;
    const int tid = threadIdx.x;
    const int tx  = tid & 15;
    const int ty  = tid >> 4;

    float acc[8][4];
#pragma unroll
    for (int i = 0; i < 8; i++)
#pragma unroll
        for (int j = 0; j < 4; j++) acc[i][j] = 0.0f;

    for (int k0 = 0; k0 < HID; k0 += 16) {
#pragma unroll
        for (int it = 0; it < 2; it++) {
            int idx = tid + it * 256;
            int m   = idx >> 2;
            int kg  = idx & 3;
            float4 v = *(const float4*)(x + (size_t)(tm0 + m) * HID + k0 + kg * 4);
            As[kg*4+0][m] = v.x;
            As[kg*4+1][m] = v.y;
            As[kg*4+2][m] = v.z;
            As[kg*4+3][m] = v.w;
        }
        {
            int k  = tid >> 4;
            int cg = tid & 15;
            *(float4*)&Bs[k][cg*4] =
                *(const float4*)(W + (size_t)(k0 + k) * HID + c0 + cg * 4);
        }
        __syncthreads();

#pragma unroll
        for (int k = 0; k < 16; k++) {
            float a[8], b[4];
#pragma unroll
            for (int i = 0; i < 8; i++) a[i] = As[k][ty + 16*i];
#pragma unroll
            for (int j = 0; j < 4; j++) b[j] = Bs[k][tx + 16*j];
#pragma unroll
            for (int i = 0; i < 8; i++)
#pragma unroll
                for (int j = 0; j < 4; j++) acc[i][j] += a[i] * b[j];
        }
        __syncthreads();
    }

#pragma unroll
    for (int i = 0; i < 8; i++) {
        int t = tm0 + ty + 16*i;
        int b = t >> 12;
        int n = t & (NN - 1);
#pragma unroll
        for (int j = 0; j < 4; j++) {
            int c = c0 + tx + 16*j;
            float val = (acc[i][j] + bias[c]) * scale;
            int h = c >> 6;
            int d = c & 63;
            // pre-round to tf32 so the attention hot loop needs no converts
            outb[(((size_t)(b * NH + h)) * NN + n) * HD + d] =
                __uint_as_float(f2tf(val));
        }
    }
}

// ---------------------------------------------------------------------------
// Kernel 2: flash attention on tensor cores (tf32 mma.sync, fp32 accum).
// Block: 128 queries of one (b,h); 4 warps, each warp = 32 query rows (2 m16).
// K-tile 64, online softmax in fragment registers, P via warp-private smem.
// Grid: (B*NH=16, N/128=32). Dynamic smem ~103 KB, 2 blocks/SM.
// ---------------------------------------------------------------------------
#define QSS 68
#define KSS 68
#define VSS 72
#define PSS 68
#define ATTN_SMEM ((128*QSS + 64*KSS + 64*VSS + 128*PSS + 64) * (int)sizeof(float))

__global__ __launch_bounds__(128, 2) void attn_mma_kernel(const float* __restrict__ mask)
{
    extern __shared__ float sm[];
    float* Qs  = sm;                    // [128 q][68]  row-major
    float* Ks  = Qs + 128*QSS;          // [64 kk][68]
    float* Vs  = Ks + 64*KSS;           // [64 c][72]
    float* Ps  = Vs + 64*VSS;           // [128 q][68]  (warp-private rows)
    float* mks = Ps + 128*PSS;          // [64] key mask

    const int bh  = blockIdx.x;
    const int b   = bh >> 3;
    const int h   = bh & 7;
    const int qt0 = blockIdx.y * 128;
    const int tid  = threadIdx.x;
    const int warp = tid >> 5;
    const int lane = tid & 31;
    const int g  = lane >> 2;   // groupID (row within fragment)
    const int tg = lane & 3;    // thread-in-group (col within fragment)
    const int qbase = warp * 32;

    const float* qb = g_q + (size_t)bh * NN * HD;
    const float* kb = g_k + (size_t)bh * NN * HD;
    const float* vb = g_v + (size_t)bh * NN * HD;
    const float* mb = mask + (size_t)b * NN;

    // Load Q tile [128 x 64] row-major into smem (coalesced float4)
    for (int idx = tid; idx < 128 * 16; idx += 128) {
        int r = idx >> 4, dg = idx & 15;
        *(float4*)(Qs + r*QSS + dg*4) =
            *(const float4*)(qb + (size_t)(qt0 + r) * HD + dg * 4);
    }

    float S[2][8][4];     // [m-tile][n-tile][frag reg]
    float O[2][8][4];     // [m-tile][d-tile][frag reg]
    float mrow[2][2], lrow[2][2], mq[2][2];
#pragma unroll
    for (int mt = 0; mt < 2; mt++) {
#pragma unroll
        for (int r = 0; r < 2; r++) {
            mrow[mt][r] = -1e30f;
            lrow[mt][r] = 0.0f;
            mq[mt][r]   = mb[qt0 + qbase + mt*16 + r*8 + g];
        }
#pragma unroll
        for (int dt = 0; dt < 8; dt++)
#pragma unroll
            for (int j = 0; j < 4; j++) O[mt][dt][j] = 0.0f;
    }

    for (int kt0 = 0; kt0 < NN; kt0 += 64) {
        // Load K, V tiles (straight row-major copies) + key mask
        for (int idx = tid; idx < 64 * 16; idx += 128) {
            int c = idx >> 4, dg = idx & 15;
            *(float4*)(Ks + c*KSS + dg*4) =
                *(const float4*)(kb + (size_t)(kt0 + c) * HD + dg * 4);
            *(float4*)(Vs + c*VSS + dg*4) =
                *(const float4*)(vb + (size_t)(kt0 + c) * HD + dg * 4);
        }
        if (tid < 64) mks[tid] = mb[kt0 + tid];
        __syncthreads();

        // ---- S = Q @ K^T  (m32 x n64 per warp) ----
#pragma unroll
        for (int mt = 0; mt < 2; mt++)
#pragma unroll
            for (int nt = 0; nt < 8; nt++)
#pragma unroll
                for (int j = 0; j < 4; j++) S[mt][nt][j] = 0.0f;

#pragma unroll
        for (int ks = 0; ks < 8; ks++) {
            unsigned a[2][4], bf[8][2];
#pragma unroll
            for (int mt = 0; mt < 2; mt++) {
                const float* base = Qs + (qbase + mt*16)*QSS + ks*8;
                a[mt][0] = __float_as_uint(base[g*QSS + tg]);
                a[mt][1] = __float_as_uint(base[(g+8)*QSS + tg]);
                a[mt][2] = __float_as_uint(base[g*QSS + tg + 4]);
                a[mt][3] = __float_as_uint(base[(g+8)*QSS + tg + 4]);
            }
#pragma unroll
            for (int nt = 0; nt < 8; nt++) {
                const float* base = Ks + (nt*8 + g)*KSS + ks*8;
                bf[nt][0] = __float_as_uint(base[tg]);
                bf[nt][1] = __float_as_uint(base[tg + 4]);
            }
#pragma unroll
            for (int mt = 0; mt < 2; mt++)
#pragma unroll
                for (int nt = 0; nt < 8; nt++)
                    mma_tf32(&S[mt][nt][0], a[mt], bf[nt]);
        }

        // ---- mask bias ----
#pragma unroll
        for (int nt = 0; nt < 8; nt++) {
            int cb = nt*8 + tg*2;
            float mk0 = mks[cb], mk1 = mks[cb + 1];
#pragma unroll
            for (int mt = 0; mt < 2; mt++) {
                S[mt][nt][0] += (1.0f - mq[mt][0]*mk0) * (-1.0e6f);
                S[mt][nt][1] += (1.0f - mq[mt][0]*mk1) * (-1.0e6f);
                S[mt][nt][2] += (1.0f - mq[mt][1]*mk0) * (-1.0e6f);
                S[mt][nt][3] += (1.0f - mq[mt][1]*mk1) * (-1.0e6f);
            }
        }

        // ---- online softmax (per row), write P (tf32-rounded) to smem ----
#pragma unroll
        for (int mt = 0; mt < 2; mt++) {
#pragma unroll
            for (int r = 0; r < 2; r++) {
                float tmax = -1e30f;
#pragma unroll
                for (int nt = 0; nt < 8; nt++)
                    tmax = fmaxf(tmax, fmaxf(S[mt][nt][2*r], S[mt][nt][2*r+1]));
                tmax = fmaxf(tmax, __shfl_xor_sync(0xffffffffu, tmax, 1));
                tmax = fmaxf(tmax, __shfl_xor_sync(0xffffffffu, tmax, 2));

                float mnew = fmaxf(mrow[mt][r], tmax);
                float fac  = __expf(mrow[mt][r] - mnew);
                float rsum = 0.0f;
                int prow = qbase + mt*16 + r*8 + g;
#pragma unroll
                for (int nt = 0; nt < 8; nt++) {
                    float p0 = __expf(S[mt][nt][2*r]   - mnew);
                    float p1 = __expf(S[mt][nt][2*r+1] - mnew);
                    rsum += p0 + p1;
                    float2 pp = make_float2(__uint_as_float(f2tf(p0)),
                                            __uint_as_float(f2tf(p1)));
                    *(float2*)(Ps + prow*PSS + nt*8 + tg*2) = pp;
                }
                rsum += __shfl_xor_sync(0xffffffffu, rsum, 1);
                rsum += __shfl_xor_sync(0xffffffffu, rsum, 2);

                lrow[mt][r] = lrow[mt][r]*fac + rsum;
                mrow[mt][r] = mnew;
#pragma unroll
                for (int dt = 0; dt < 8; dt++) {
                    O[mt][dt][2*r]   *= fac;
                    O[mt][dt][2*r+1] *= fac;
                }
            }
        }
        __syncwarp();   // P rows are warp-private: warp-level ordering suffices

        // ---- O += P @ V  (k = 64 key positions) ----
#pragma unroll
        for (int ks = 0; ks < 8; ks++) {
            unsigned a[2][4], bf[8][2];
#pragma unroll
            for (int mt = 0; mt < 2; mt++) {
                const float* base = Ps + (qbase + mt*16)*PSS + ks*8;
                a[mt][0] = __float_as_uint(base[g*PSS + tg]);
                a[mt][1] = __float_as_uint(base[(g+8)*PSS + tg]);
                a[mt][2] = __float_as_uint(base[g*PSS + tg + 4]);
                a[mt][3] = __float_as_uint(base[(g+8)*PSS + tg + 4]);
            }
#pragma unroll
            for (int dt = 0; dt < 8; dt++) {
                const float* base = Vs + (ks*8 + tg)*VSS + dt*8;
                bf[dt][0] = __float_as_uint(base[g]);
                bf[dt][1] = __float_as_uint(base[4*VSS + g]);
            }
#pragma unroll
            for (int mt = 0; mt < 2; mt++)
#pragma unroll
                for (int dt = 0; dt < 8; dt++)
                    mma_tf32(&O[mt][dt][0], a[mt], bf[dt]);
        }
        __syncthreads();   // before next iteration overwrites Ks/Vs
    }

    // ---- epilogue: normalize, write [t, h*64+d] ----
#pragma unroll
    for (int mt = 0; mt < 2; mt++) {
#pragma unroll
        for (int r = 0; r < 2; r++) {
            float inv = 1.0f / lrow[mt][r];
            int row = qt0 + qbase + mt*16 + r*8 + g;
            float* op = g_attn + ((size_t)(b * NN + row)) * HID + h * HD;
#pragma unroll
            for (int dt = 0; dt < 8; dt++) {
                float2 v = make_float2(O[mt][dt][2*r] * inv,
                                       O[mt][dt][2*r+1] * inv);
                *(float2*)(op + dt*8 + tg*2) = v;
            }
        }
    }
}

// ---------------------------------------------------------------------------
// Kernel 3: output projection (SIMT fp32).
// ---------------------------------------------------------------------------
__global__ __launch_bounds__(256) void proj_kernel(
    const float* __restrict__ Wo, const float* __restrict__ bo,
    float* __restrict__ out)
{
    __shared__ float As[16][129];
    __shared__ float Bs[16][64];

    const int c0  = blockIdx.x * 64;
    const int tm0 = blockIdx.y * 128;
    const int tid = threadIdx.x;
    const int tx  = tid & 15;
    const int ty  = tid >> 4;

    float acc[8][4];
#pragma unroll
    for (int i = 0; i < 8; i++)
#pragma unroll
        for (int j = 0; j < 4; j++) acc[i][j] = 0.0f;

    for (int k0 = 0; k0 < HID; k0 += 16) {
#pragma unroll
        for (int it = 0; it < 2; it++) {
            int idx = tid + it * 256;
            int m   = idx >> 2;
            int kg  = idx & 3;
            float4 v = *(const float4*)(g_attn + (size_t)(tm0 + m) * HID + k0 + kg * 4);
            As[kg*4+0][m] = v.x;
            As[kg*4+1][m] = v.y;
            As[kg*4+2][m] = v.z;
            As[kg*4+3][m] = v.w;
        }
        {
            int k  = tid >> 4;
            int cg = tid & 15;
            *(float4*)&Bs[k][cg*4] =
                *(const float4*)(Wo + (size_t)(k0 + k) * HID + c0 + cg * 4);
        }
        __syncthreads();

#pragma unroll
        for (int k = 0; k < 16; k++) {
            float a[8], b[4];
#pragma unroll
            for (int i = 0; i < 8; i++) a[i] = As[k][ty + 16*i];
#pragma unroll
            for (int j = 0; j < 4; j++) b[j] = Bs[k][tx + 16*j];
#pragma unroll
            for (int i = 0; i < 8; i++)
#pragma unroll
                for (int j = 0; j < 4; j++) acc[i][j] += a[i] * b[j];
        }
        __syncthreads();
    }

#pragma unroll
    for (int i = 0; i < 8; i++) {
        int t = tm0 + ty + 16*i;
#pragma unroll
        for (int j = 0; j < 4; j++) {
            int c = c0 + tx + 16*j;
            out[(size_t)t * HID + c] = acc[i][j] + bo[c];
        }
    }
}

// ---------------------------------------------------------------------------
extern "C" void kernel_launch(void* const* d_in, const int* in_sizes, int n_in,
                              void* d_out, int out_size)
{
    const float* x    = (const float*)d_in[0];
    const float* mask = (const float*)d_in[1];
    const float* Wq   = (const float*)d_in[2];
    const float* bq   = (const float*)d_in[3];
    const float* Wk   = (const float*)d_in[4];
    const float* bk   = (const float*)d_in[5];
    const float* Wv   = (const float*)d_in[6];
    const float* bv   = (const float*)d_in[7];
    const float* Wo   = (const float*)d_in[8];
    const float* bo   = (const float*)d_in[9];
    float* out = (float*)d_out;

    cudaFuncSetAttribute(attn_mma_kernel,
                         cudaFuncAttributeMaxDynamicSharedMemorySize, ATTN_SMEM);

    dim3 qkv_grid(24, MTOK / 128);
    qkv_kernel<<<qkv_grid, 256>>>(x, Wq, bq, Wk, bk, Wv, bv);

    dim3 attn_grid(BB * NH, NN / 128);
    attn_mma_kernel<<<attn_grid, 128, ATTN_SMEM>>>(mask);

    dim3 proj_grid(HID / 64, MTOK / 128);
    proj_kernel<<<proj_grid, 256>>>(Wo, bo, out);
}

// round 4
// speedup vs baseline: 3.0128x; 1.2224x over previous
#include <cuda_runtime.h>
#include <math.h>

// Problem constants
#define BB   2
#define NN   4096
#define HID  512
#define NH   8
#define HD   64
#define MTOK (BB*NN)          // 8192 tokens
#define QSCALE 0.04419417382415922f   // 1/sqrt(512)

// Scratch (device globals; no allocations allowed)
static __device__ float g_q[(size_t)BB*NH*NN*HD];     // [b,h,n,d]  tf32-rounded
static __device__ float g_k[(size_t)BB*NH*NN*HD];     // tf32-rounded
static __device__ float g_v[(size_t)BB*NH*NN*HD];     // tf32-rounded
static __device__ float g_attn[(size_t)MTOK*HID];     // [t, h*64+d] fp32

// ---------------------------------------------------------------------------
// Helpers
// ---------------------------------------------------------------------------
__device__ __forceinline__ unsigned f2tf(float f) {
    unsigned u;
    asm("cvt.rna.tf32.f32 %0, %1;" : "=r"(u) : "f"(f));
    return u;
}

// split v into tf32 hi + fp32 lo (lo = v - hi, exact)
__device__ __forceinline__ void tf_split(float v, unsigned& hi, unsigned& lo) {
    unsigned h = f2tf(v);
    float lof = v - __uint_as_float(h);
    hi = h;
    lo = __float_as_uint(lof);   // implicit RZ truncation in MMA: fine (2^-24 level)
}

__device__ __forceinline__ void mma_tf32(float* d, const unsigned* a, const unsigned* b) {
    asm volatile(
        "mma.sync.aligned.m16n8k8.row.col.f32.tf32.tf32.f32 "
        "{%0,%1,%2,%3}, {%4,%5,%6,%7}, {%8,%9}, {%0,%1,%2,%3};"
        : "+f"(d[0]), "+f"(d[1]), "+f"(d[2]), "+f"(d[3])
        : "r"(a[0]), "r"(a[1]), "r"(a[2]), "r"(a[3]), "r"(b[0]), "r"(b[1]));
}

__device__ __forceinline__ void cp_async16(void* smem, const void* gmem) {
    unsigned sa = (unsigned)__cvta_generic_to_shared(smem);
    asm volatile("cp.async.cg.shared.global [%0], [%1], 16;" :: "r"(sa), "l"(gmem));
}
#define CP_COMMIT() asm volatile("cp.async.commit_group;")
#define CP_WAIT1()  asm volatile("cp.async.wait_group 1;")
#define CP_WAIT0()  asm volatile("cp.async.wait_group 0;")

// ===========================================================================
// 3xTF32 tensor-core GEMM core (fp32-accurate): 128x128 block, 8 warps
// (4m x 2n), each warp m32 x n64. K=512 in chunks of 16, 2-stage cp.async.
// Per fragment element: hi/lo split; D += hi*hi + hi*lo + lo*hi.
// ===========================================================================
#define ASТRIDE 20
#define BSTRIDE 136

struct GemmFrag { float S[2][8][4]; };

__device__ __forceinline__ void gemm_128x128_3x(
    const float* __restrict__ A, const float* __restrict__ Bw,
    int tm0, int c0,
    float (*AsBuf)[128*ASТRIDE], float (*BsBuf)[16*BSTRIDE],
    GemmFrag& fr)
{
    const int tid  = threadIdx.x;
    const int warp = tid >> 5;
    const int lane = tid & 31;
    const int g  = lane >> 2;
    const int tg = lane & 3;
    const int wm0 = (warp >> 1) * 32;
    const int wn0 = (warp & 1) * 64;

#pragma unroll
    for (int mt = 0; mt < 2; mt++)
#pragma unroll
        for (int nt = 0; nt < 8; nt++)
#pragma unroll
            for (int j = 0; j < 4; j++) fr.S[mt][nt][j] = 0.0f;

    const int lm  = tid >> 2;
    const int lkg = tid & 3;
    const int lk  = tid >> 5;
    const int lcg = tid & 31;

    {
        const float* a0 = A + (size_t)(tm0 + lm) * HID + lkg * 4;
        cp_async16(&AsBuf[0][lm*ASТRIDE + lkg*4], a0);
        cp_async16(&AsBuf[0][(lm+64)*ASТRIDE + lkg*4], a0 + (size_t)64*HID);
        const float* b0 = Bw + (size_t)lk * HID + c0 + lcg * 4;
        cp_async16(&BsBuf[0][lk*BSTRIDE + lcg*4], b0);
        cp_async16(&BsBuf[0][(lk+8)*BSTRIDE + lcg*4], b0 + (size_t)8*HID);
        CP_COMMIT();
    }

    for (int kc = 0; kc < 32; kc++) {
        __syncthreads();
        if (kc + 1 < 32) {
            int s  = (kc + 1) & 1;
            int k0 = (kc + 1) * 16;
            const float* a0 = A + (size_t)(tm0 + lm) * HID + k0 + lkg * 4;
            cp_async16(&AsBuf[s][lm*ASТRIDE + lkg*4], a0);
            cp_async16(&AsBuf[s][(lm+64)*ASТRIDE + lkg*4], a0 + (size_t)64*HID);
            const float* b0 = Bw + (size_t)(k0 + lk) * HID + c0 + lcg * 4;
            cp_async16(&BsBuf[s][lk*BSTRIDE + lcg*4], b0);
            cp_async16(&BsBuf[s][(lk+8)*BSTRIDE + lcg*4], b0 + (size_t)8*HID);
            CP_COMMIT();
            CP_WAIT1();
        } else {
            CP_WAIT0();
        }
        __syncthreads();

        const float* As = AsBuf[kc & 1];
        const float* Bs = BsBuf[kc & 1];
#pragma unroll
        for (int ks = 0; ks < 2; ks++) {
            unsigned ahi[2][4], alo[2][4];
#pragma unroll
            for (int mt = 0; mt < 2; mt++) {
                const float* base = As + (wm0 + mt*16)*ASТRIDE + ks*8;
                tf_split(base[g*ASТRIDE + tg],         ahi[mt][0], alo[mt][0]);
                tf_split(base[(g+8)*ASТRIDE + tg],     ahi[mt][1], alo[mt][1]);
                tf_split(base[g*ASТRIDE + tg + 4],     ahi[mt][2], alo[mt][2]);
                tf_split(base[(g+8)*ASТRIDE + tg + 4], ahi[mt][3], alo[mt][3]);
            }
#pragma unroll
            for (int nt = 0; nt < 8; nt++) {
                const float* base = Bs + (ks*8 + tg)*BSTRIDE + wn0 + nt*8;
                unsigned bhi[2], blo[2];
                tf_split(base[g],           bhi[0], blo[0]);
                tf_split(base[4*BSTRIDE + g], bhi[1], blo[1]);
#pragma unroll
                for (int mt = 0; mt < 2; mt++) {
                    mma_tf32(&fr.S[mt][nt][0], ahi[mt], bhi);   // hi*hi
                    mma_tf32(&fr.S[mt][nt][0], ahi[mt], blo);   // hi*lo
                    mma_tf32(&fr.S[mt][nt][0], alo[mt], bhi);   // lo*hi
                }
            }
        }
    }
}

// ---------------------------------------------------------------------------
// Kernel 1: fused QKV projection (3xTF32 tensor cores).
// Grid: x = 12 (3 weights x 4 col-tiles of 128), y = 64 row tiles.
// ---------------------------------------------------------------------------
__global__ __launch_bounds__(256) void qkv_mma_kernel(
    const float* __restrict__ x,
    const float* __restrict__ Wq, const float* __restrict__ bq,
    const float* __restrict__ Wk, const float* __restrict__ bk,
    const float* __restrict__ Wv, const float* __restrict__ bv)
{
    __shared__ float AsBuf[2][128*ASТRIDE];
    __shared__ float BsBuf[2][16*BSTRIDE];

    const int wsel = blockIdx.x >> 2;          // 0=q,1=k,2=v
    const int c0   = (blockIdx.x & 3) * 128;
    const float* W    = (wsel==0) ? Wq : ((wsel==1) ? Wk : Wv);
    const float* bias = (wsel==0) ? bq : ((wsel==1) ? bk : bv);
    float* outb       = (wsel==0) ? g_q : ((wsel==1) ? g_k : g_v);
    const float scale = (wsel==0) ? QSCALE : 1.0f;
    const int tm0 = blockIdx.y * 128;

    GemmFrag fr;
    gemm_128x128_3x(x, W, tm0, c0, AsBuf, BsBuf, fr);

    const int tid  = threadIdx.x;
    const int warp = tid >> 5;
    const int lane = tid & 31;
    const int g  = lane >> 2;
    const int tg = lane & 3;
    const int wm0 = (warp >> 1) * 32;
    const int wn0 = (warp & 1) * 64;

    const int cbase = c0 + wn0;            // head-aligned 64-col span
    const int h = cbase >> 6;

#pragma unroll
    for (int mt = 0; mt < 2; mt++) {
#pragma unroll
        for (int r = 0; r < 2; r++) {
            int t = tm0 + wm0 + mt*16 + r*8 + g;
            int b = t >> 12;
            int n = t & (NN - 1);
            float* op = outb + (((size_t)(b * NH + h)) * NN + n) * HD;
#pragma unroll
            for (int nt = 0; nt < 8; nt++) {
                int d0 = nt*8 + tg*2;
                float v0 = (fr.S[mt][nt][2*r]   + bias[cbase + d0])     * scale;
                float v1 = (fr.S[mt][nt][2*r+1] + bias[cbase + d0 + 1]) * scale;
                // pre-round to tf32 for the attention kernel's MMA operands
                float2 vv = make_float2(__uint_as_float(f2tf(v0)),
                                        __uint_as_float(f2tf(v1)));
                *(float2*)(op + d0) = vv;
            }
        }
    }
}

// ---------------------------------------------------------------------------
// Kernel 3: output projection (3xTF32 tensor cores).
// ---------------------------------------------------------------------------
__global__ __launch_bounds__(256) void proj_mma_kernel(
    const float* __restrict__ Wo, const float* __restrict__ bo,
    float* __restrict__ out)
{
    __shared__ float AsBuf[2][128*ASТRIDE];
    __shared__ float BsBuf[2][16*BSTRIDE];

    const int c0  = blockIdx.x * 128;
    const int tm0 = blockIdx.y * 128;

    GemmFrag fr;
    gemm_128x128_3x(g_attn, Wo, tm0, c0, AsBuf, BsBuf, fr);

    const int tid  = threadIdx.x;
    const int warp = tid >> 5;
    const int lane = tid & 31;
    const int g  = lane >> 2;
    const int tg = lane & 3;
    const int wm0 = (warp >> 1) * 32;
    const int wn0 = (warp & 1) * 64;

#pragma unroll
    for (int mt = 0; mt < 2; mt++) {
#pragma unroll
        for (int r = 0; r < 2; r++) {
            int t = tm0 + wm0 + mt*16 + r*8 + g;
            float* op = out + (size_t)t * HID + c0 + wn0;
#pragma unroll
            for (int nt = 0; nt < 8; nt++) {
                int d0 = nt*8 + tg*2;
                float2 vv = make_float2(fr.S[mt][nt][2*r]   + bo[c0 + wn0 + d0],
                                        fr.S[mt][nt][2*r+1] + bo[c0 + wn0 + d0 + 1]);
                *(float2*)(op + d0) = vv;
            }
        }
    }
}

// ---------------------------------------------------------------------------
// Kernel 2: flash attention on tensor cores (unchanged; validated at 2.6e-4).
// ---------------------------------------------------------------------------
#define QSS 68
#define KSS 68
#define VSS 72
#define PSS 68
#define ATTN_SMEM ((128*QSS + 64*KSS + 64*VSS + 128*PSS + 64) * (int)sizeof(float))

__global__ __launch_bounds__(128, 2) void attn_mma_kernel(const float* __restrict__ mask)
{
    extern __shared__ float sm[];
    float* Qs  = sm;                    // [128 q][68]
    float* Ks  = Qs + 128*QSS;          // [64 kk][68]
    float* Vs  = Ks + 64*KSS;           // [64 c][72]
    float* Ps  = Vs + 64*VSS;           // [128 q][68]
    float* mks = Ps + 128*PSS;          // [64]

    const int bh  = blockIdx.x;
    const int b   = bh >> 3;
    const int h   = bh & 7;
    const int qt0 = blockIdx.y * 128;
    const int tid  = threadIdx.x;
    const int warp = tid >> 5;
    const int lane = tid & 31;
    const int g  = lane >> 2;
    const int tg = lane & 3;
    const int qbase = warp * 32;

    const float* qb = g_q + (size_t)bh * NN * HD;
    const float* kb = g_k + (size_t)bh * NN * HD;
    const float* vb = g_v + (size_t)bh * NN * HD;
    const float* mb = mask + (size_t)b * NN;

    for (int idx = tid; idx < 128 * 16; idx += 128) {
        int r = idx >> 4, dg = idx & 15;
        *(float4*)(Qs + r*QSS + dg*4) =
            *(const float4*)(qb + (size_t)(qt0 + r) * HD + dg * 4);
    }

    float S[2][8][4];
    float O[2][8][4];
    float mrow[2][2], lrow[2][2], mq[2][2];
#pragma unroll
    for (int mt = 0; mt < 2; mt++) {
#pragma unroll
        for (int r = 0; r < 2; r++) {
            mrow[mt][r] = -1e30f;
            lrow[mt][r] = 0.0f;
            mq[mt][r]   = mb[qt0 + qbase + mt*16 + r*8 + g];
        }
#pragma unroll
        for (int dt = 0; dt < 8; dt++)
#pragma unroll
            for (int j = 0; j < 4; j++) O[mt][dt][j] = 0.0f;
    }

    for (int kt0 = 0; kt0 < NN; kt0 += 64) {
        for (int idx = tid; idx < 64 * 16; idx += 128) {
            int c = idx >> 4, dg = idx & 15;
            *(float4*)(Ks + c*KSS + dg*4) =
                *(const float4*)(kb + (size_t)(kt0 + c) * HD + dg * 4);
            *(float4*)(Vs + c*VSS + dg*4) =
                *(const float4*)(vb + (size_t)(kt0 + c) * HD + dg * 4);
        }
        if (tid < 64) mks[tid] = mb[kt0 + tid];
        __syncthreads();

#pragma unroll
        for (int mt = 0; mt < 2; mt++)
#pragma unroll
            for (int nt = 0; nt < 8; nt++)
#pragma unroll
                for (int j = 0; j < 4; j++) S[mt][nt][j] = 0.0f;

#pragma unroll
        for (int ks = 0; ks < 8; ks++) {
            unsigned a[2][4], bf[8][2];
#pragma unroll
            for (int mt = 0; mt < 2; mt++) {
                const float* base = Qs + (qbase + mt*16)*QSS + ks*8;
                a[mt][0] = __float_as_uint(base[g*QSS + tg]);
                a[mt][1] = __float_as_uint(base[(g+8)*QSS + tg]);
                a[mt][2] = __float_as_uint(base[g*QSS + tg + 4]);
                a[mt][3] = __float_as_uint(base[(g+8)*QSS + tg + 4]);
            }
#pragma unroll
            for (int nt = 0; nt < 8; nt++) {
                const float* base = Ks + (nt*8 + g)*KSS + ks*8;
                bf[nt][0] = __float_as_uint(base[tg]);
                bf[nt][1] = __float_as_uint(base[tg + 4]);
            }
#pragma unroll
            for (int mt = 0; mt < 2; mt++)
#pragma unroll
                for (int nt = 0; nt < 8; nt++)
                    mma_tf32(&S[mt][nt][0], a[mt], bf[nt]);
        }

#pragma unroll
        for (int nt = 0; nt < 8; nt++) {
            int cb = nt*8 + tg*2;
            float mk0 = mks[cb], mk1 = mks[cb + 1];
#pragma unroll
            for (int mt = 0; mt < 2; mt++) {
                S[mt][nt][0] += (1.0f - mq[mt][0]*mk0) * (-1.0e6f);
                S[mt][nt][1] += (1.0f - mq[mt][0]*mk1) * (-1.0e6f);
                S[mt][nt][2] += (1.0f - mq[mt][1]*mk0) * (-1.0e6f);
                S[mt][nt][3] += (1.0f - mq[mt][1]*mk1) * (-1.0e6f);
            }
        }

#pragma unroll
        for (int mt = 0; mt < 2; mt++) {
#pragma unroll
            for (int r = 0; r < 2; r++) {
                float tmax = -1e30f;
#pragma unroll
                for (int nt = 0; nt < 8; nt++)
                    tmax = fmaxf(tmax, fmaxf(S[mt][nt][2*r], S[mt][nt][2*r+1]));
                tmax = fmaxf(tmax, __shfl_xor_sync(0xffffffffu, tmax, 1));
                tmax = fmaxf(tmax, __shfl_xor_sync(0xffffffffu, tmax, 2));

                float mnew = fmaxf(mrow[mt][r], tmax);
                float fac  = __expf(mrow[mt][r] - mnew);
                float rsum = 0.0f;
                int prow = qbase + mt*16 + r*8 + g;
#pragma unroll
                for (int nt = 0; nt < 8; nt++) {
                    float p0 = __expf(S[mt][nt][2*r]   - mnew);
                    float p1 = __expf(S[mt][nt][2*r+1] - mnew);
                    rsum += p0 + p1;
                    float2 pp = make_float2(__uint_as_float(f2tf(p0)),
                                            __uint_as_float(f2tf(p1)));
                    *(float2*)(Ps + prow*PSS + nt*8 + tg*2) = pp;
                }
                rsum += __shfl_xor_sync(0xffffffffu, rsum, 1);
                rsum += __shfl_xor_sync(0xffffffffu, rsum, 2);

                lrow[mt][r] = lrow[mt][r]*fac + rsum;
                mrow[mt][r] = mnew;
#pragma unroll
                for (int dt = 0; dt < 8; dt++) {
                    O[mt][dt][2*r]   *= fac;
                    O[mt][dt][2*r+1] *= fac;
                }
            }
        }
        __syncwarp();

#pragma unroll
        for (int ks = 0; ks < 8; ks++) {
            unsigned a[2][4], bf[8][2];
#pragma unroll
            for (int mt = 0; mt < 2; mt++) {
                const float* base = Ps + (qbase + mt*16)*PSS + ks*8;
                a[mt][0] = __float_as_uint(base[g*PSS + tg]);
                a[mt][1] = __float_as_uint(base[(g+8)*PSS + tg]);
                a[mt][2] = __float_as_uint(base[g*PSS + tg + 4]);
                a[mt][3] = __float_as_uint(base[(g+8)*PSS + tg + 4]);
            }
#pragma unroll
            for (int dt = 0; dt < 8; dt++) {
                const float* base = Vs + (ks*8 + tg)*VSS + dt*8;
                bf[dt][0] = __float_as_uint(base[g]);
                bf[dt][1] = __float_as_uint(base[4*VSS + g]);
            }
#pragma unroll
            for (int mt = 0; mt < 2; mt++)
#pragma unroll
                for (int dt = 0; dt < 8; dt++)
                    mma_tf32(&O[mt][dt][0], a[mt], bf[dt]);
        }
        __syncthreads();
    }

#pragma unroll
    for (int mt = 0; mt < 2; mt++) {
#pragma unroll
        for (int r = 0; r < 2; r++) {
            float inv = 1.0f / lrow[mt][r];
            int row = qt0 + qbase + mt*16 + r*8 + g;
            float* op = g_attn + ((size_t)(b * NN + row)) * HID + h * HD;
#pragma unroll
            for (int dt = 0; dt < 8; dt++) {
                float2 v = make_float2(O[mt][dt][2*r] * inv,
                                       O[mt][dt][2*r+1] * inv);
                *(float2*)(op + dt*8 + tg*2) = v;
            }
        }
    }
}

// ---------------------------------------------------------------------------
extern "C" void kernel_launch(void* const* d_in, const int* in_sizes, int n_in,
                              void* d_out, int out_size)
{
    const float* x    = (const float*)d_in[0];
    const float* mask = (const float*)d_in[1];
    const float* Wq   = (const float*)d_in[2];
    const float* bq   = (const float*)d_in[3];
    const float* Wk   = (const float*)d_in[4];
    const float* bk   = (const float*)d_in[5];
    const float* Wv   = (const float*)d_in[6];
    const float* bv   = (const float*)d_in[7];
    const float* Wo   = (const float*)d_in[8];
    const float* bo   = (const float*)d_in[9];
    float* out = (float*)d_out;

    cudaFuncSetAttribute(attn_mma_kernel,
                         cudaFuncAttributeMaxDynamicSharedMemorySize, ATTN_SMEM);

    dim3 qkv_grid(12, MTOK / 128);
    qkv_mma_kernel<<<qkv_grid, 256>>>(x, Wq, bq, Wk, bk, Wv, bv);

    dim3 attn_grid(BB * NH, NN / 128);
    attn_mma_kernel<<<attn_grid, 128, ATTN_SMEM>>>(mask);

    dim3 proj_grid(HID / 128, MTOK / 128);
    proj_mma_kernel<<<proj_grid, 256>>>(Wo, bo, out);
}

// round 7
// speedup vs baseline: 4.2963x; 1.4260x over previous
#include <cuda_runtime.h>
#include <cuda_fp16.h>
#include <math.h>
#include <stdint.h>

// Problem constants
#define BB   2
#define NN   4096
#define HID  512
#define NH   8
#define HD   64
#define MTOK (BB*NN)          // 8192 tokens
#define QSCALE 0.04419417382415922f   // 1/sqrt(512)

// Scratch (device globals; no allocations allowed)
static __device__ __half g_q[(size_t)BB*NH*NN*HD];    // [b,h,n,d] fp16
static __device__ __half g_k[(size_t)BB*NH*NN*HD];    // [b,h,n,d] fp16
static __device__ __half g_v[(size_t)BB*NH*NN*HD];    // [b,h,n,d] fp16
static __device__ float  g_attn[(size_t)MTOK*HID];    // [t, h*64+d] fp32

// ---------------------------------------------------------------------------
// Helpers
// ---------------------------------------------------------------------------
__device__ __forceinline__ unsigned f2tf(float f) {
    unsigned u;
    asm("cvt.rna.tf32.f32 %0, %1;" : "=r"(u) : "f"(f));
    return u;
}
__device__ __forceinline__ void tf_split(float v, unsigned& hi, unsigned& lo) {
    unsigned h = f2tf(v);
    float lof = v - __uint_as_float(h);
    hi = h;
    lo = __float_as_uint(lof);
}
__device__ __forceinline__ void mma_tf32(float* d, const unsigned* a, const unsigned* b) {
    asm volatile(
        "mma.sync.aligned.m16n8k8.row.col.f32.tf32.tf32.f32 "
        "{%0,%1,%2,%3}, {%4,%5,%6,%7}, {%8,%9}, {%0,%1,%2,%3};"
        : "+f"(d[0]), "+f"(d[1]), "+f"(d[2]), "+f"(d[3])
        : "r"(a[0]), "r"(a[1]), "r"(a[2]), "r"(a[3]), "r"(b[0]), "r"(b[1]));
}
__device__ __forceinline__ void mma_f16(float* d, const unsigned* a, const unsigned* b) {
    asm volatile(
        "mma.sync.aligned.m16n8k16.row.col.f32.f16.f16.f32 "
        "{%0,%1,%2,%3}, {%4,%5,%6,%7}, {%8,%9}, {%0,%1,%2,%3};"
        : "+f"(d[0]), "+f"(d[1]), "+f"(d[2]), "+f"(d[3])
        : "r"(a[0]), "r"(a[1]), "r"(a[2]), "r"(a[3]), "r"(b[0]), "r"(b[1]));
}
__device__ __forceinline__ void ldmx2t(uint32_t& r0, uint32_t& r1, uint32_t saddr) {
    asm volatile("ldmatrix.sync.aligned.m8n8.x2.trans.shared.b16 {%0,%1}, [%2];"
                 : "=r"(r0), "=r"(r1) : "r"(saddr));
}
__device__ __forceinline__ void cp_async16(void* smem, const void* gmem) {
    unsigned sa = (unsigned)__cvta_generic_to_shared(smem);
    asm volatile("cp.async.cg.shared.global [%0], [%1], 16;" :: "r"(sa), "l"(gmem));
}
__device__ __forceinline__ void cp_async16_u(unsigned saddr, const void* gmem) {
    asm volatile("cp.async.cg.shared.global [%0], [%1], 16;" :: "r"(saddr), "l"(gmem));
}
#define CP_COMMIT() asm volatile("cp.async.commit_group;")
#define CP_WAIT1()  asm volatile("cp.async.wait_group 1;")
#define CP_WAIT0()  asm volatile("cp.async.wait_group 0;")

// ===========================================================================
// 3xTF32 tensor-core GEMM core (validated round 4)
// ===========================================================================
#define ASТRIDE 20
#define BSTRIDE 136

struct GemmFrag { float S[2][8][4]; };

__device__ __forceinline__ void gemm_128x128_3x(
    const float* __restrict__ A, const float* __restrict__ Bw,
    int tm0, int c0,
    float (*AsBuf)[128*ASТRIDE], float (*BsBuf)[16*BSTRIDE],
    GemmFrag& fr)
{
    const int tid  = threadIdx.x;
    const int warp = tid >> 5;
    const int lane = tid & 31;
    const int g  = lane >> 2;
    const int tg = lane & 3;
    const int wm0 = (warp >> 1) * 32;
    const int wn0 = (warp & 1) * 64;

#pragma unroll
    for (int mt = 0; mt < 2; mt++)
#pragma unroll
        for (int nt = 0; nt < 8; nt++)
#pragma unroll
            for (int j = 0; j < 4; j++) fr.S[mt][nt][j] = 0.0f;

    const int lm  = tid >> 2;
    const int lkg = tid & 3;
    const int lk  = tid >> 5;
    const int lcg = tid & 31;

    {
        const float* a0 = A + (size_t)(tm0 + lm) * HID + lkg * 4;
        cp_async16(&AsBuf[0][lm*ASТRIDE + lkg*4], a0);
        cp_async16(&AsBuf[0][(lm+64)*ASТRIDE + lkg*4], a0 + (size_t)64*HID);
        const float* b0 = Bw + (size_t)lk * HID + c0 + lcg * 4;
        cp_async16(&BsBuf[0][lk*BSTRIDE + lcg*4], b0);
        cp_async16(&BsBuf[0][(lk+8)*BSTRIDE + lcg*4], b0 + (size_t)8*HID);
        CP_COMMIT();
    }

    for (int kc = 0; kc < 32; kc++) {
        __syncthreads();
        if (kc + 1 < 32) {
            int s  = (kc + 1) & 1;
            int k0 = (kc + 1) * 16;
            const float* a0 = A + (size_t)(tm0 + lm) * HID + k0 + lkg * 4;
            cp_async16(&AsBuf[s][lm*ASТRIDE + lkg*4], a0);
            cp_async16(&AsBuf[s][(lm+64)*ASТRIDE + lkg*4], a0 + (size_t)64*HID);
            const float* b0 = Bw + (size_t)(k0 + lk) * HID + c0 + lcg * 4;
            cp_async16(&BsBuf[s][lk*BSTRIDE + lcg*4], b0);
            cp_async16(&BsBuf[s][(lk+8)*BSTRIDE + lcg*4], b0 + (size_t)8*HID);
            CP_COMMIT();
            CP_WAIT1();
        } else {
            CP_WAIT0();
        }
        __syncthreads();

        const float* As = AsBuf[kc & 1];
        const float* Bs = BsBuf[kc & 1];
#pragma unroll
        for (int ks = 0; ks < 2; ks++) {
            unsigned ahi[2][4], alo[2][4];
#pragma unroll
            for (int mt = 0; mt < 2; mt++) {
                const float* base = As + (wm0 + mt*16)*ASТRIDE + ks*8;
                tf_split(base[g*ASТRIDE + tg],         ahi[mt][0], alo[mt][0]);
                tf_split(base[(g+8)*ASТRIDE + tg],     ahi[mt][1], alo[mt][1]);
                tf_split(base[g*ASТRIDE + tg + 4],     ahi[mt][2], alo[mt][2]);
                tf_split(base[(g+8)*ASТRIDE + tg + 4], ahi[mt][3], alo[mt][3]);
            }
#pragma unroll
            for (int nt = 0; nt < 8; nt++) {
                const float* base = Bs + (ks*8 + tg)*BSTRIDE + wn0 + nt*8;
                unsigned bhi[2], blo[2];
                tf_split(base[g],             bhi[0], blo[0]);
                tf_split(base[4*BSTRIDE + g], bhi[1], blo[1]);
#pragma unroll
                for (int mt = 0; mt < 2; mt++) {
                    mma_tf32(&fr.S[mt][nt][0], ahi[mt], bhi);
                    mma_tf32(&fr.S[mt][nt][0], ahi[mt], blo);
                    mma_tf32(&fr.S[mt][nt][0], alo[mt], bhi);
                }
            }
        }
    }
}

// ---------------------------------------------------------------------------
// Kernel 1: fused QKV projection (3xTF32). Outputs fp16 [b,h,n,d].
// ---------------------------------------------------------------------------
__global__ __launch_bounds__(256) void qkv_mma_kernel(
    const float* __restrict__ x,
    const float* __restrict__ Wq, const float* __restrict__ bq,
    const float* __restrict__ Wk, const float* __restrict__ bk,
    const float* __restrict__ Wv, const float* __restrict__ bv)
{
    __shared__ float AsBuf[2][128*ASТRIDE];
    __shared__ float BsBuf[2][16*BSTRIDE];

    const int wsel = blockIdx.x >> 2;          // 0=q,1=k,2=v
    const int c0   = (blockIdx.x & 3) * 128;
    const float* W    = (wsel==0) ? Wq : ((wsel==1) ? Wk : Wv);
    const float* bias = (wsel==0) ? bq : ((wsel==1) ? bk : bv);
    __half* outb      = (wsel==0) ? g_q : ((wsel==1) ? g_k : g_v);
    const float scale = (wsel==0) ? QSCALE : 1.0f;
    const int tm0 = blockIdx.y * 128;

    GemmFrag fr;
    gemm_128x128_3x(x, W, tm0, c0, AsBuf, BsBuf, fr);

    const int tid  = threadIdx.x;
    const int warp = tid >> 5;
    const int lane = tid & 31;
    const int g  = lane >> 2;
    const int tg = lane & 3;
    const int wm0 = (warp >> 1) * 32;
    const int wn0 = (warp & 1) * 64;

    const int cbase = c0 + wn0;            // head-aligned 64-col span
    const int h = cbase >> 6;

#pragma unroll
    for (int mt = 0; mt < 2; mt++) {
#pragma unroll
        for (int r = 0; r < 2; r++) {
            int t = tm0 + wm0 + mt*16 + r*8 + g;
            int b = t >> 12;
            int n = t & (NN - 1);
            __half* op = outb + (((size_t)(b * NH + h)) * NN + n) * HD;
#pragma unroll
            for (int nt = 0; nt < 8; nt++) {
                int d0 = nt*8 + tg*2;
                float v0 = (fr.S[mt][nt][2*r]   + bias[cbase + d0])     * scale;
                float v1 = (fr.S[mt][nt][2*r+1] + bias[cbase + d0 + 1]) * scale;
                *(__half2*)(op + d0) = __floats2half2_rn(v0, v1);
            }
        }
    }
}

// ---------------------------------------------------------------------------
// Kernel 3: output projection (3xTF32). Unchanged.
// ---------------------------------------------------------------------------
__global__ __launch_bounds__(256) void proj_mma_kernel(
    const float* __restrict__ Wo, const float* __restrict__ bo,
    float* __restrict__ out)
{
    __shared__ float AsBuf[2][128*ASТRIDE];
    __shared__ float BsBuf[2][16*BSTRIDE];

    const int c0  = blockIdx.x * 128;
    const int tm0 = blockIdx.y * 128;

    GemmFrag fr;
    gemm_128x128_3x(g_attn, Wo, tm0, c0, AsBuf, BsBuf, fr);

    const int tid  = threadIdx.x;
    const int warp = tid >> 5;
    const int lane = tid & 31;
    const int g  = lane >> 2;
    const int tg = lane & 3;
    const int wm0 = (warp >> 1) * 32;
    const int wn0 = (warp & 1) * 64;

#pragma unroll
    for (int mt = 0; mt < 2; mt++) {
#pragma unroll
        for (int r = 0; r < 2; r++) {
            int t = tm0 + wm0 + mt*16 + r*8 + g;
            float* op = out + (size_t)t * HID + c0 + wn0;
#pragma unroll
            for (int nt = 0; nt < 8; nt++) {
                int d0 = nt*8 + tg*2;
                float2 vv = make_float2(fr.S[mt][nt][2*r]   + bo[c0 + wn0 + d0],
                                        fr.S[mt][nt][2*r+1] + bo[c0 + wn0 + d0 + 1]);
                *(float2*)(op + d0) = vv;
            }
        }
    }
}

// ===========================================================================
// Kernel 2: flash attention, fp16 mma.sync m16n8k16 (fp32 accum).
// CTA = one (b,h) x 128 queries; 4 warps x 32 rows; 64-key tiles, 64 of them.
// No max-tracking (scores bounded); cp.async double buffering; V row-major
// consumed via ldmatrix.x2.trans.
// SMEM halfs, pitch QP=72: Q[128] | K[2][64] | V[2][64] | P[128] | mask[2][64]f
// ===========================================================================
#define QP 72
#define AOFF_Q  0
#define AOFF_K  (128*QP*2)                 // bytes
#define AOFF_V  (AOFF_K + 2*64*QP*2)
#define AOFF_P  (AOFF_V + 2*64*QP*2)
#define AOFF_MK (AOFF_P + 128*QP*2)
#define ATTN_SMEM (AOFF_MK + 2*64*4)
#define KVBUF (64*QP*2)                    // bytes per K/V buffer

__global__ __launch_bounds__(128, 2) void attn_fp16_kernel(const float* __restrict__ mask)
{
    extern __shared__ char smc[];
    const uint32_t sbase = (uint32_t)__cvta_generic_to_shared(smc);
    __half* Qs = (__half*)(smc + AOFF_Q);
    __half* Ps = (__half*)(smc + AOFF_P);

    const int tid  = threadIdx.x;
    const int warp = tid >> 5;
    const int lane = tid & 31;
    const int g  = lane >> 2;
    const int tg = lane & 3;
    const int wq0 = warp * 32;

    const int bh  = blockIdx.x;
    const int b   = bh >> 3;
    const int h   = bh & 7;
    const int qt0 = blockIdx.y * 128;

    const __half* qb = g_q + (size_t)bh * NN * HD;
    const __half* kb = g_k + (size_t)bh * NN * HD;
    const __half* vb = g_v + (size_t)bh * NN * HD;
    const float*  mb = mask + (size_t)b * NN;

    // prologue: Q + tile 0 (K/V/mask) in one cp.async group
    for (int i = tid; i < 1024; i += 128) {
        int row = i >> 3, ch = i & 7;
        cp_async16_u(sbase + AOFF_Q + row*(QP*2) + ch*16,
                     qb + (size_t)(qt0 + row) * HD + ch*8);
    }
    for (int i = tid; i < 512; i += 128) {
        int row = i >> 3, ch = i & 7;
        cp_async16_u(sbase + AOFF_K + row*(QP*2) + ch*16, kb + (size_t)row * HD + ch*8);
        cp_async16_u(sbase + AOFF_V + row*(QP*2) + ch*16, vb + (size_t)row * HD + ch*8);
    }
    if (tid < 16) cp_async16_u(sbase + AOFF_MK + tid*16, mb + tid*4);
    CP_COMMIT();

    float mq[2][2];
#pragma unroll
    for (int mt = 0; mt < 2; mt++)
#pragma unroll
        for (int r = 0; r < 2; r++)
            mq[mt][r] = mb[qt0 + wq0 + mt*16 + r*8 + g];

    float O[2][8][4];
#pragma unroll
    for (int mt = 0; mt < 2; mt++)
#pragma unroll
        for (int dt = 0; dt < 8; dt++)
#pragma unroll
            for (int j = 0; j < 4; j++) O[mt][dt][j] = 0.0f;
    float lsum[2][2] = {{0.f,0.f},{0.f,0.f}};

    for (int it = 0; it < 64; it++) {
        const int buf = it & 1;
        __syncthreads();   // all warps done computing on buffer (it+1)&1
        if (it + 1 < 64) {
            const int nb = (it + 1) & 1;
            const __half* kg = kb + (size_t)(it + 1) * 64 * HD;
            const __half* vg = vb + (size_t)(it + 1) * 64 * HD;
            for (int i = tid; i < 512; i += 128) {
                int row = i >> 3, ch = i & 7;
                cp_async16_u(sbase + AOFF_K + nb*KVBUF + row*(QP*2) + ch*16,
                             kg + (size_t)row * HD + ch*8);
                cp_async16_u(sbase + AOFF_V + nb*KVBUF + row*(QP*2) + ch*16,
                             vg + (size_t)row * HD + ch*8);
            }
            if (tid < 16) cp_async16_u(sbase + AOFF_MK + nb*256 + tid*16,
                                       mb + (it + 1)*64 + tid*4);
            CP_COMMIT();
            CP_WAIT1();
        } else {
            CP_WAIT0();
        }
        __syncthreads();   // tile `it` visible

        const __half* Ksb = (__half*)(smc + AOFF_K + buf*KVBUF);
        const float*  mks = (const float*)(smc + AOFF_MK + buf*256);

        // ---- S = Q @ K^T  (4 k-chunks of 16) ----
        float S[2][8][4];
#pragma unroll
        for (int mt = 0; mt < 2; mt++)
#pragma unroll
            for (int nt = 0; nt < 8; nt++)
#pragma unroll
                for (int j = 0; j < 4; j++) S[mt][nt][j] = 0.0f;

#pragma unroll
        for (int kc = 0; kc < 4; kc++) {
            uint32_t a[2][4];
#pragma unroll
            for (int mt = 0; mt < 2; mt++) {
                const __half* base = Qs + (wq0 + mt*16)*QP + kc*16;
                a[mt][0] = *(const uint32_t*)(base + g*QP + 2*tg);
                a[mt][1] = *(const uint32_t*)(base + (g+8)*QP + 2*tg);
                a[mt][2] = *(const uint32_t*)(base + g*QP + 2*tg + 8);
                a[mt][3] = *(const uint32_t*)(base + (g+8)*QP + 2*tg + 8);
            }
#pragma unroll
            for (int nt = 0; nt < 8; nt++) {
                const __half* bb = Ksb + (nt*8 + g)*QP + kc*16;
                uint32_t bf[2];
                bf[0] = *(const uint32_t*)(bb + 2*tg);
                bf[1] = *(const uint32_t*)(bb + 2*tg + 8);
#pragma unroll
                for (int mt = 0; mt < 2; mt++)
                    mma_f16(&S[mt][nt][0], a[mt], bf);
            }
        }

        // ---- softmax (no max subtraction; masked -> exp(-1e6) = 0) ----
#pragma unroll
        for (int mt = 0; mt < 2; mt++) {
#pragma unroll
            for (int nt = 0; nt < 8; nt++) {
                int c0 = nt*8 + 2*tg;
                float mk0 = mks[c0], mk1 = mks[c0 + 1];
                float p0 = __expf(S[mt][nt][0] + (1.0f - mq[mt][0]*mk0) * (-1.0e6f));
                float p1 = __expf(S[mt][nt][1] + (1.0f - mq[mt][0]*mk1) * (-1.0e6f));
                float p2 = __expf(S[mt][nt][2] + (1.0f - mq[mt][1]*mk0) * (-1.0e6f));
                float p3 = __expf(S[mt][nt][3] + (1.0f - mq[mt][1]*mk1) * (-1.0e6f));
                lsum[mt][0] += p0 + p1;
                lsum[mt][1] += p2 + p3;
                *(__half2*)(Ps + (wq0 + mt*16 + g)*QP + c0)     = __floats2half2_rn(p0, p1);
                *(__half2*)(Ps + (wq0 + mt*16 + g + 8)*QP + c0) = __floats2half2_rn(p2, p3);
            }
        }
        __syncwarp();      // P rows warp-private

        // ---- O += P @ V  (4 k-chunks of 16 keys; B via ldmatrix.x2.trans) ----
        const uint32_t vbase = sbase + AOFF_V + buf*KVBUF;
#pragma unroll
        for (int kc = 0; kc < 4; kc++) {
            uint32_t a[2][4];
#pragma unroll
            for (int mt = 0; mt < 2; mt++) {
                const __half* base = Ps + (wq0 + mt*16)*QP + kc*16;
                a[mt][0] = *(const uint32_t*)(base + g*QP + 2*tg);
                a[mt][1] = *(const uint32_t*)(base + (g+8)*QP + 2*tg);
                a[mt][2] = *(const uint32_t*)(base + g*QP + 2*tg + 8);
                a[mt][3] = *(const uint32_t*)(base + (g+8)*QP + 2*tg + 8);
            }
#pragma unroll
            for (int dt = 0; dt < 8; dt++) {
                uint32_t b0, b1;
                uint32_t addr = vbase + (uint32_t)((kc*16 + (lane & 15))*(QP*2) + dt*16);
                ldmx2t(b0, b1, addr);
                uint32_t bf[2] = {b0, b1};
#pragma unroll
                for (int mt = 0; mt < 2; mt++)
                    mma_f16(&O[mt][dt][0], a[mt], bf);
            }
        }
    }

    // ---- epilogue: row sums (reduce over 4 tg lanes), normalize, store ----
#pragma unroll
    for (int mt = 0; mt < 2; mt++) {
#pragma unroll
        for (int r = 0; r < 2; r++) {
            float s = lsum[mt][r];
            s += __shfl_xor_sync(0xffffffffu, s, 1);
            s += __shfl_xor_sync(0xffffffffu, s, 2);
            float inv = 1.0f / s;
            int row = qt0 + wq0 + mt*16 + r*8 + g;
            float* op = g_attn + ((size_t)(b * NN + row)) * HID + h * HD;
#pragma unroll
            for (int dt = 0; dt < 8; dt++) {
                float2 v = make_float2(O[mt][dt][2*r] * inv,
                                       O[mt][dt][2*r+1] * inv);
                *(float2*)(op + dt*8 + 2*tg) = v;
            }
        }
    }
}

// ---------------------------------------------------------------------------
extern "C" void kernel_launch(void* const* d_in, const int* in_sizes, int n_in,
                              void* d_out, int out_size)
{
    const float* x    = (const float*)d_in[0];
    const float* mask = (const float*)d_in[1];
    const float* Wq   = (const float*)d_in[2];
    const float* bq   = (const float*)d_in[3];
    const float* Wk   = (const float*)d_in[4];
    const float* bk   = (const float*)d_in[5];
    const float* Wv   = (const float*)d_in[6];
    const float* bv   = (const float*)d_in[7];
    const float* Wo   = (const float*)d_in[8];
    const float* bo   = (const float*)d_in[9];
    float* out = (float*)d_out;

    cudaFuncSetAttribute(attn_fp16_kernel,
                         cudaFuncAttributeMaxDynamicSharedMemorySize, ATTN_SMEM);

    dim3 qkv_grid(12, MTOK / 128);
    qkv_mma_kernel<<<qkv_grid, 256>>>(x, Wq, bq, Wk, bk, Wv, bv);

    dim3 attn_grid(BB * NH, NN / 128);
    attn_fp16_kernel<<<attn_grid, 128, ATTN_SMEM>>>(mask);

    dim3 proj_grid(HID / 128, MTOK / 128);
    proj_mma_kernel<<<proj_grid, 256>>>(Wo, bo, out);
}

// round 8
// speedup vs baseline: 5.3477x; 1.2447x over previous
#include <cuda_runtime.h>
#include <cuda_fp16.h>
#include <math.h>
#include <stdint.h>

// Problem constants
#define BB   2
#define NN   4096
#define HID  512
#define NH   8
#define HD   64
#define MTOK (BB*NN)          // 8192 tokens
#define QSCALE 0.04419417382415922f   // 1/sqrt(512)

// Scratch (device globals; no allocations allowed)
static __device__ __half g_xh[(size_t)MTOK*HID], g_xl[(size_t)MTOK*HID];   // x split
static __device__ __half g_wth[(size_t)3*HID*HID], g_wtl[(size_t)3*HID*HID]; // Wq/Wk/Wv transposed [n][k] split
static __device__ __half g_woth[(size_t)HID*HID], g_wotl[(size_t)HID*HID];   // Wo transposed split
static __device__ __half g_q[(size_t)BB*NH*NN*HD];    // [b,h,n,d] fp16
static __device__ __half g_k[(size_t)BB*NH*NN*HD];
static __device__ __half g_v[(size_t)BB*NH*NN*HD];
static __device__ __half g_ah[(size_t)MTOK*HID], g_al[(size_t)MTOK*HID];   // attention out split

// ---------------------------------------------------------------------------
// Helpers
// ---------------------------------------------------------------------------
__device__ __forceinline__ void mma_f16(float* d, const unsigned* a, const unsigned* b) {
    asm volatile(
        "mma.sync.aligned.m16n8k16.row.col.f32.f16.f16.f32 "
        "{%0,%1,%2,%3}, {%4,%5,%6,%7}, {%8,%9}, {%0,%1,%2,%3};"
        : "+f"(d[0]), "+f"(d[1]), "+f"(d[2]), "+f"(d[3])
        : "r"(a[0]), "r"(a[1]), "r"(a[2]), "r"(a[3]), "r"(b[0]), "r"(b[1]));
}
__device__ __forceinline__ void ldmx2t(uint32_t& r0, uint32_t& r1, uint32_t saddr) {
    asm volatile("ldmatrix.sync.aligned.m8n8.x2.trans.shared.b16 {%0,%1}, [%2];"
                 : "=r"(r0), "=r"(r1) : "r"(saddr));
}
__device__ __forceinline__ void cp_async16_u(unsigned saddr, const void* gmem) {
    asm volatile("cp.async.cg.shared.global [%0], [%1], 16;" :: "r"(saddr), "l"(gmem));
}
#define CP_COMMIT() asm volatile("cp.async.commit_group;")
#define CP_WAIT1()  asm volatile("cp.async.wait_group 1;")
#define CP_WAIT0()  asm volatile("cp.async.wait_group 0;")

__device__ __forceinline__ void f16_split(float v, __half& hi, __half& lo) {
    hi = __float2half_rn(v);
    lo = __float2half_rn(v - __half2float(hi));
}

// ---------------------------------------------------------------------------
// Prep kernel A: split x into fp16 hi/lo planes. 1M float4s.
// ---------------------------------------------------------------------------
__global__ __launch_bounds__(256) void split_x_kernel(const float* __restrict__ x)
{
    int i = blockIdx.x * 256 + threadIdx.x;       // 0 .. 1048575
    float4 v = ((const float4*)x)[i];
    __half hx, lx, hy, ly, hz, lz, hw, lw;
    f16_split(v.x, hx, lx);
    f16_split(v.y, hy, ly);
    f16_split(v.z, hz, lz);
    f16_split(v.w, hw, lw);
    ((__half2*)g_xh)[i*2]   = __halves2half2(hx, hy);
    ((__half2*)g_xh)[i*2+1] = __halves2half2(hz, hw);
    ((__half2*)g_xl)[i*2]   = __halves2half2(lx, ly);
    ((__half2*)g_xl)[i*2+1] = __halves2half2(lz, lw);
}

// ---------------------------------------------------------------------------
// Prep kernel B: transpose + split the 4 weight matrices.
// Grid (16,16,4), block (32,8). Output Wt[n][k] hi/lo fp16.
// ---------------------------------------------------------------------------
__global__ __launch_bounds__(256) void split_w_kernel(
    const float* __restrict__ Wq, const float* __restrict__ Wk,
    const float* __restrict__ Wv, const float* __restrict__ Wo)
{
    __shared__ float t[32][33];
    const int z = blockIdx.z;
    const float* W = (z==0) ? Wq : (z==1) ? Wk : (z==2) ? Wv : Wo;
    __half* dh = (z < 3) ? (g_wth + (size_t)z * HID * HID) : g_woth;
    __half* dl = (z < 3) ? (g_wtl + (size_t)z * HID * HID) : g_wotl;
    const int n0 = blockIdx.x * 32, k0 = blockIdx.y * 32;
    const int tx = threadIdx.x, ty = threadIdx.y;

#pragma unroll
    for (int r = 0; r < 4; r++)
        t[ty + r*8][tx] = W[(size_t)(k0 + ty + r*8) * HID + n0 + tx];
    __syncthreads();
#pragma unroll
    for (int r = 0; r < 4; r++) {
        float v = t[tx][ty + r*8];     // = W[k0+tx][n0+ty+r*8]
        __half hv, lv;
        f16_split(v, hv, lv);
        size_t o = (size_t)(n0 + ty + r*8) * HID + k0 + tx;
        dh[o] = hv;
        dl[o] = lv;
    }
}

// ===========================================================================
// split-fp16 GEMM core: C[128m x 128n] = A[M x 512] @ B^T (B stored [n][k]).
// A, B each as hi/lo fp16 planes. 3 HMMAs per (mt,nt): hh + hl + lh.
// 8 warps (4m x 2n), warp m32 x n64; k-chunks of 32, 2-stage cp.async.
// Dynamic smem: 8 planes of 128 x KP halves.
// ===========================================================================
#define KP 40                       // halves pitch (conflict-free, 16B-aligned rows)
#define PLANE (128*KP)              // halves per plane buffer
#define PB (PLANE*2)                // bytes per plane buffer
#define GSMEM_BYTES (8*PB)          // 81920

__device__ __forceinline__ void gemm_f16split(
    const __half* __restrict__ Agh, const __half* __restrict__ Agl,  // [M][512]
    const __half* __restrict__ Bgh, const __half* __restrict__ Bgl,  // [512 n][512 k]
    int tm0, int c0, __half* sm, float (*S)[8][4])
{
    const int tid  = threadIdx.x;
    const int warp = tid >> 5;
    const int lane = tid & 31;
    const int g  = lane >> 2;
    const int tg = lane & 3;
    const int wm0 = (warp >> 1) * 32;
    const int wn0 = (warp & 1) * 64;
    const uint32_t sb = (uint32_t)__cvta_generic_to_shared(sm);

#pragma unroll
    for (int mt = 0; mt < 2; mt++)
#pragma unroll
        for (int nt = 0; nt < 8; nt++)
#pragma unroll
            for (int j = 0; j < 4; j++) S[mt][nt][j] = 0.0f;

    // stage loader: 512 16B-chunks per plane, 4 planes
#define LOAD_STAGE(st, k0)                                                     \
    for (int i = tid; i < 512; i += 256) {                                     \
        int row = i >> 2, ch = i & 3;                                          \
        uint32_t so = (uint32_t)((st)*PB + row*(KP*2) + ch*16);                \
        size_t ga = (size_t)(tm0 + row) * HID + (k0) + ch*8;                   \
        size_t gb = (size_t)(c0  + row) * HID + (k0) + ch*8;                   \
        cp_async16_u(sb + so,        Agh + ga);                                \
        cp_async16_u(sb + 2*PB + so, Agl + ga);                                \
        cp_async16_u(sb + 4*PB + so, Bgh + gb);                                \
        cp_async16_u(sb + 6*PB + so, Bgl + gb);                                \
    }

    LOAD_STAGE(0, 0)
    CP_COMMIT();

    for (int kc = 0; kc < 16; kc++) {
        __syncthreads();
        if (kc + 1 < 16) {
            int ns = (kc + 1) & 1;
            int nk = (kc + 1) * 32;
            LOAD_STAGE(ns, nk)
            CP_COMMIT();
            CP_WAIT1();
        } else {
            CP_WAIT0();
        }
        __syncthreads();

        const int st = kc & 1;
        const __half* Ah = sm + st*PLANE;
        const __half* Al = sm + 2*PLANE + st*PLANE;
        const __half* Bh = sm + 4*PLANE + st*PLANE;
        const __half* Bl = sm + 6*PLANE + st*PLANE;

#pragma unroll
        for (int ks = 0; ks < 2; ks++) {
            const int ko = ks * 16;
            uint32_t ahi[2][4], alo[2][4];
#pragma unroll
            for (int mt = 0; mt < 2; mt++) {
                const __half* ah = Ah + (wm0 + mt*16)*KP + ko;
                const __half* al = Al + (wm0 + mt*16)*KP + ko;
                ahi[mt][0] = *(const uint32_t*)(ah + g*KP + 2*tg);
                ahi[mt][1] = *(const uint32_t*)(ah + (g+8)*KP + 2*tg);
                ahi[mt][2] = *(const uint32_t*)(ah + g*KP + 2*tg + 8);
                ahi[mt][3] = *(const uint32_t*)(ah + (g+8)*KP + 2*tg + 8);
                alo[mt][0] = *(const uint32_t*)(al + g*KP + 2*tg);
                alo[mt][1] = *(const uint32_t*)(al + (g+8)*KP + 2*tg);
                alo[mt][2] = *(const uint32_t*)(al + g*KP + 2*tg + 8);
                alo[mt][3] = *(const uint32_t*)(al + (g+8)*KP + 2*tg + 8);
            }
#pragma unroll
            for (int nt = 0; nt < 8; nt++) {
                const __half* bh = Bh + (wn0 + nt*8 + g)*KP + ko;
                const __half* bl = Bl + (wn0 + nt*8 + g)*KP + ko;
                uint32_t bhi[2], blo[2];
                bhi[0] = *(const uint32_t*)(bh + 2*tg);
                bhi[1] = *(const uint32_t*)(bh + 2*tg + 8);
                blo[0] = *(const uint32_t*)(bl + 2*tg);
                blo[1] = *(const uint32_t*)(bl + 2*tg + 8);
#pragma unroll
                for (int mt = 0; mt < 2; mt++) {
                    mma_f16(&S[mt][nt][0], ahi[mt], bhi);   // hi*hi
                    mma_f16(&S[mt][nt][0], ahi[mt], blo);   // hi*lo
                    mma_f16(&S[mt][nt][0], alo[mt], bhi);   // lo*hi
                }
            }
        }
    }
#undef LOAD_STAGE
}

// ---------------------------------------------------------------------------
// Kernel 1: fused QKV projection (split-fp16). Outputs fp16 [b,h,n,d].
// Grid (12, 64): x = 3 weights x 4 col-tiles of 128, y = row tiles.
// ---------------------------------------------------------------------------
__global__ __launch_bounds__(256, 2) void qkv_f16_kernel(
    const float* __restrict__ bq, const float* __restrict__ bk,
    const float* __restrict__ bv)
{
    extern __shared__ __half gsm[];
    const int wsel = blockIdx.x >> 2;
    const int c0   = (blockIdx.x & 3) * 128;
    const __half* Bh = g_wth + (size_t)wsel * HID * HID;
    const __half* Bl = g_wtl + (size_t)wsel * HID * HID;
    const float* bias = (wsel==0) ? bq : ((wsel==1) ? bk : bv);
    __half* outb      = (wsel==0) ? g_q : ((wsel==1) ? g_k : g_v);
    const float scale = (wsel==0) ? QSCALE : 1.0f;
    const int tm0 = blockIdx.y * 128;

    float S[2][8][4];
    gemm_f16split(g_xh, g_xl, Bh, Bl, tm0, c0, gsm, S);

    const int tid  = threadIdx.x;
    const int warp = tid >> 5;
    const int lane = tid & 31;
    const int g  = lane >> 2;
    const int tg = lane & 3;
    const int wm0 = (warp >> 1) * 32;
    const int wn0 = (warp & 1) * 64;

    const int cbase = c0 + wn0;            // head-aligned 64-col span
    const int hh = cbase >> 6;

#pragma unroll
    for (int mt = 0; mt < 2; mt++) {
#pragma unroll
        for (int r = 0; r < 2; r++) {
            int t = tm0 + wm0 + mt*16 + r*8 + g;
            int b = t >> 12;
            int n = t & (NN - 1);
            __half* op = outb + (((size_t)(b * NH + hh)) * NN + n) * HD;
#pragma unroll
            for (int nt = 0; nt < 8; nt++) {
                int d0 = nt*8 + tg*2;
                float v0 = (S[mt][nt][2*r]   + bias[cbase + d0])     * scale;
                float v1 = (S[mt][nt][2*r+1] + bias[cbase + d0 + 1]) * scale;
                *(__half2*)(op + d0) = __floats2half2_rn(v0, v1);
            }
        }
    }
}

// ---------------------------------------------------------------------------
// Kernel 3: output projection (split-fp16). fp32 out.
// Grid (4, 64).
// ---------------------------------------------------------------------------
__global__ __launch_bounds__(256, 2) void proj_f16_kernel(
    const float* __restrict__ bo, float* __restrict__ out)
{
    extern __shared__ __half gsm[];
    const int c0  = blockIdx.x * 128;
    const int tm0 = blockIdx.y * 128;

    float S[2][8][4];
    gemm_f16split(g_ah, g_al, g_woth, g_wotl, tm0, c0, gsm, S);

    const int tid  = threadIdx.x;
    const int warp = tid >> 5;
    const int lane = tid & 31;
    const int g  = lane >> 2;
    const int tg = lane & 3;
    const int wm0 = (warp >> 1) * 32;
    const int wn0 = (warp & 1) * 64;

#pragma unroll
    for (int mt = 0; mt < 2; mt++) {
#pragma unroll
        for (int r = 0; r < 2; r++) {
            int t = tm0 + wm0 + mt*16 + r*8 + g;
            float* op = out + (size_t)t * HID + c0 + wn0;
#pragma unroll
            for (int nt = 0; nt < 8; nt++) {
                int d0 = nt*8 + tg*2;
                float2 vv = make_float2(S[mt][nt][2*r]   + bo[c0 + wn0 + d0],
                                        S[mt][nt][2*r+1] + bo[c0 + wn0 + d0 + 1]);
                *(float2*)(op + d0) = vv;
            }
        }
    }
}

// ===========================================================================
// Kernel 2: flash attention, fp16 mma.sync (validated round 7).
// Only change: epilogue writes hi/lo fp16 planes g_ah/g_al.
// ===========================================================================
#define QP 72
#define AOFF_Q  0
#define AOFF_K  (128*QP*2)                 // bytes
#define AOFF_V  (AOFF_K + 2*64*QP*2)
#define AOFF_P  (AOFF_V + 2*64*QP*2)
#define AOFF_MK (AOFF_P + 128*QP*2)
#define ATTN_SMEM (AOFF_MK + 2*64*4)
#define KVBUF (64*QP*2)                    // bytes per K/V buffer

__global__ __launch_bounds__(128, 2) void attn_fp16_kernel(const float* __restrict__ mask)
{
    extern __shared__ char smc[];
    const uint32_t sbase = (uint32_t)__cvta_generic_to_shared(smc);
    __half* Qs = (__half*)(smc + AOFF_Q);
    __half* Ps = (__half*)(smc + AOFF_P);

    const int tid  = threadIdx.x;
    const int warp = tid >> 5;
    const int lane = tid & 31;
    const int g  = lane >> 2;
    const int tg = lane & 3;
    const int wq0 = warp * 32;

    const int bh  = blockIdx.x;
    const int b   = bh >> 3;
    const int hd  = bh & 7;
    const int qt0 = blockIdx.y * 128;

    const __half* qb = g_q + (size_t)bh * NN * HD;
    const __half* kb = g_k + (size_t)bh * NN * HD;
    const __half* vb = g_v + (size_t)bh * NN * HD;
    const float*  mb = mask + (size_t)b * NN;

    // prologue: Q + tile 0 (K/V/mask) in one cp.async group
    for (int i = tid; i < 1024; i += 128) {
        int row = i >> 3, ch = i & 7;
        cp_async16_u(sbase + AOFF_Q + row*(QP*2) + ch*16,
                     qb + (size_t)(qt0 + row) * HD + ch*8);
    }
    for (int i = tid; i < 512; i += 128) {
        int row = i >> 3, ch = i & 7;
        cp_async16_u(sbase + AOFF_K + row*(QP*2) + ch*16, kb + (size_t)row * HD + ch*8);
        cp_async16_u(sbase + AOFF_V + row*(QP*2) + ch*16, vb + (size_t)row * HD + ch*8);
    }
    if (tid < 16) cp_async16_u(sbase + AOFF_MK + tid*16, mb + tid*4);
    CP_COMMIT();

    float mq[2][2];
#pragma unroll
    for (int mt = 0; mt < 2; mt++)
#pragma unroll
        for (int r = 0; r < 2; r++)
            mq[mt][r] = mb[qt0 + wq0 + mt*16 + r*8 + g];

    float O[2][8][4];
#pragma unroll
    for (int mt = 0; mt < 2; mt++)
#pragma unroll
        for (int dt = 0; dt < 8; dt++)
#pragma unroll
            for (int j = 0; j < 4; j++) O[mt][dt][j] = 0.0f;
    float lsum[2][2] = {{0.f,0.f},{0.f,0.f}};

    for (int it = 0; it < 64; it++) {
        const int buf = it & 1;
        __syncthreads();
        if (it + 1 < 64) {
            const int nb = (it + 1) & 1;
            const __half* kg = kb + (size_t)(it + 1) * 64 * HD;
            const __half* vg = vb + (size_t)(it + 1) * 64 * HD;
            for (int i = tid; i < 512; i += 128) {
                int row = i >> 3, ch = i & 7;
                cp_async16_u(sbase + AOFF_K + nb*KVBUF + row*(QP*2) + ch*16,
                             kg + (size_t)row * HD + ch*8);
                cp_async16_u(sbase + AOFF_V + nb*KVBUF + row*(QP*2) + ch*16,
                             vg + (size_t)row * HD + ch*8);
            }
            if (tid < 16) cp_async16_u(sbase + AOFF_MK + nb*256 + tid*16,
                                       mb + (it + 1)*64 + tid*4);
            CP_COMMIT();
            CP_WAIT1();
        } else {
            CP_WAIT0();
        }
        __syncthreads();

        const __half* Ksb = (__half*)(smc + AOFF_K + buf*KVBUF);
        const float*  mks = (const float*)(smc + AOFF_MK + buf*256);

        // ---- S = Q @ K^T ----
        float S[2][8][4];
#pragma unroll
        for (int mt = 0; mt < 2; mt++)
#pragma unroll
            for (int nt = 0; nt < 8; nt++)
#pragma unroll
                for (int j = 0; j < 4; j++) S[mt][nt][j] = 0.0f;

#pragma unroll
        for (int kc = 0; kc < 4; kc++) {
            uint32_t a[2][4];
#pragma unroll
            for (int mt = 0; mt < 2; mt++) {
                const __half* base = Qs + (wq0 + mt*16)*QP + kc*16;
                a[mt][0] = *(const uint32_t*)(base + g*QP + 2*tg);
                a[mt][1] = *(const uint32_t*)(base + (g+8)*QP + 2*tg);
                a[mt][2] = *(const uint32_t*)(base + g*QP + 2*tg + 8);
                a[mt][3] = *(const uint32_t*)(base + (g+8)*QP + 2*tg + 8);
            }
#pragma unroll
            for (int nt = 0; nt < 8; nt++) {
                const __half* bbk = Ksb + (nt*8 + g)*QP + kc*16;
                uint32_t bf[2];
                bf[0] = *(const uint32_t*)(bbk + 2*tg);
                bf[1] = *(const uint32_t*)(bbk + 2*tg + 8);
#pragma unroll
                for (int mt = 0; mt < 2; mt++)
                    mma_f16(&S[mt][nt][0], a[mt], bf);
            }
        }

        // ---- softmax (no max subtraction; masked -> exp(-1e6) = 0) ----
#pragma unroll
        for (int mt = 0; mt < 2; mt++) {
#pragma unroll
            for (int nt = 0; nt < 8; nt++) {
                int c0 = nt*8 + 2*tg;
                float mk0 = mks[c0], mk1 = mks[c0 + 1];
                float p0 = __expf(S[mt][nt][0] + (1.0f - mq[mt][0]*mk0) * (-1.0e6f));
                float p1 = __expf(S[mt][nt][1] + (1.0f - mq[mt][0]*mk1) * (-1.0e6f));
                float p2 = __expf(S[mt][nt][2] + (1.0f - mq[mt][1]*mk0) * (-1.0e6f));
                float p3 = __expf(S[mt][nt][3] + (1.0f - mq[mt][1]*mk1) * (-1.0e6f));
                lsum[mt][0] += p0 + p1;
                lsum[mt][1] += p2 + p3;
                *(__half2*)(Ps + (wq0 + mt*16 + g)*QP + c0)     = __floats2half2_rn(p0, p1);
                *(__half2*)(Ps + (wq0 + mt*16 + g + 8)*QP + c0) = __floats2half2_rn(p2, p3);
            }
        }
        __syncwarp();

        // ---- O += P @ V ----
        const uint32_t vbase = sbase + AOFF_V + buf*KVBUF;
#pragma unroll
        for (int kc = 0; kc < 4; kc++) {
            uint32_t a[2][4];
#pragma unroll
            for (int mt = 0; mt < 2; mt++) {
                const __half* base = Ps + (wq0 + mt*16)*QP + kc*16;
                a[mt][0] = *(const uint32_t*)(base + g*QP + 2*tg);
                a[mt][1] = *(const uint32_t*)(base + (g+8)*QP + 2*tg);
                a[mt][2] = *(const uint32_t*)(base + g*QP + 2*tg + 8);
                a[mt][3] = *(const uint32_t*)(base + (g+8)*QP + 2*tg + 8);
            }
#pragma unroll
            for (int dt = 0; dt < 8; dt++) {
                uint32_t b0, b1;
                uint32_t addr = vbase + (uint32_t)((kc*16 + (lane & 15))*(QP*2) + dt*16);
                ldmx2t(b0, b1, addr);
                uint32_t bf[2] = {b0, b1};
#pragma unroll
                for (int mt = 0; mt < 2; mt++)
                    mma_f16(&O[mt][dt][0], a[mt], bf);
            }
        }
    }

    // ---- epilogue: normalize, split to fp16 hi/lo planes ----
#pragma unroll
    for (int mt = 0; mt < 2; mt++) {
#pragma unroll
        for (int r = 0; r < 2; r++) {
            float s = lsum[mt][r];
            s += __shfl_xor_sync(0xffffffffu, s, 1);
            s += __shfl_xor_sync(0xffffffffu, s, 2);
            float inv = 1.0f / s;
            int row = qt0 + wq0 + mt*16 + r*8 + g;
            size_t base = ((size_t)(b * NN + row)) * HID + hd * HD;
#pragma unroll
            for (int dt = 0; dt < 8; dt++) {
                float v0 = O[mt][dt][2*r] * inv;
                float v1 = O[mt][dt][2*r+1] * inv;
                __half h0, l0, h1, l1;
                f16_split(v0, h0, l0);
                f16_split(v1, h1, l1);
                size_t o = base + dt*8 + 2*tg;
                *(__half2*)(g_ah + o) = __halves2half2(h0, h1);
                *(__half2*)(g_al + o) = __halves2half2(l0, l1);
            }
        }
    }
}

// ---------------------------------------------------------------------------
extern "C" void kernel_launch(void* const* d_in, const int* in_sizes, int n_in,
                              void* d_out, int out_size)
{
    const float* x    = (const float*)d_in[0];
    const float* mask = (const float*)d_in[1];
    const float* Wq   = (const float*)d_in[2];
    const float* bq   = (const float*)d_in[3];
    const float* Wk   = (const float*)d_in[4];
    const float* bk   = (const float*)d_in[5];
    const float* Wv   = (const float*)d_in[6];
    const float* bv   = (const float*)d_in[7];
    const float* Wo   = (const float*)d_in[8];
    const float* bo   = (const float*)d_in[9];
    float* out = (float*)d_out;

    cudaFuncSetAttribute(attn_fp16_kernel,
                         cudaFuncAttributeMaxDynamicSharedMemorySize, ATTN_SMEM);
    cudaFuncSetAttribute(qkv_f16_kernel,
                         cudaFuncAttributeMaxDynamicSharedMemorySize, GSMEM_BYTES);
    cudaFuncSetAttribute(proj_f16_kernel,
                         cudaFuncAttributeMaxDynamicSharedMemorySize, GSMEM_BYTES);

    split_x_kernel<<<4096, 256>>>(x);
    split_w_kernel<<<dim3(16, 16, 4), dim3(32, 8)>>>(Wq, Wk, Wv, Wo);

    dim3 qkv_grid(12, MTOK / 128);
    qkv_f16_kernel<<<qkv_grid, 256, GSMEM_BYTES>>>(bq, bk, bv);

    dim3 attn_grid(BB * NH, NN / 128);
    attn_fp16_kernel<<<attn_grid, 128, ATTN_SMEM>>>(mask);

    dim3 proj_grid(HID / 128, MTOK / 128);
    proj_f16_kernel<<<proj_grid, 256, GSMEM_BYTES>>>(bo, out);
}